// round 7
// baseline (speedup 1.0000x reference)
#include <cuda_runtime.h>
#include <math.h>
#include <float.h>

#define BB   32
#define SS   4096
#define INF_ 256
#define DD   64
#define KK   8
#define NROW (BB*SS)          // 131072
#define EPSN 1e-5f

// ---------------- scratch (device globals; no allocation allowed) ----------------
__device__ __align__(16) float g_k[NROW*DD];        // 33.5 MB
__device__ __align__(16) float g_v[NROW*DD];        // 33.5 MB
__device__ __align__(16) float g_q[BB*KK*DD];
__device__ __align__(16) float g_slots[BB*KK*DD];
__device__ __align__(16) float g_upd[BB*KK*DD];
__device__ __align__(16) float g_updp[64*BB*KK*DD]; // 64 S-chunks of partial updates (4 MB)
__device__ float g_stats[BB*KK*2];                  // {rowmax, 1/sumexp}
__device__ float g_cb[2*DD];                        // b_ln @ [Wk|Wv]

// ---------------- init: slots broadcast + epilogue bias precompute ----------------
__global__ void k_init(const float* __restrict__ slot_emb,
                       const float* __restrict__ Wk, const float* __restrict__ Wv,
                       const float* __restrict__ lnb) {
    int t = blockIdx.x*blockDim.x + threadIdx.x;
    if (t < BB*KK*DD) g_slots[t] = slot_emb[t % (KK*DD)];
    if (t < 2*DD) {
        float s = 0.f;
        for (int i = 0; i < INF_; i++) {
            float w = (t < DD) ? Wk[i*DD + t] : Wv[i*DD + (t-DD)];
            s += lnb[i]*w;
        }
        g_cb[t] = s;
    }
}

// ---------------- phase 1: fused LN + K/V projection GEMM ----------------
// 64 rows x 128 cols per block; K-chunks of 32; per-thread 4x8 register tile.
__global__ __launch_bounds__(256) void k_proj(const float* __restrict__ x,
                                              const float* __restrict__ Wk,
                                              const float* __restrict__ Wv,
                                              const float* __restrict__ gln) {
    __shared__ float xsT[32][68];     // [k][row], padded (16B-aligned float4 rows)
    __shared__ float ws[32][128];     // [k][col], g folded in
    __shared__ float rm[64], rr[64], scb[128];

    int tid  = threadIdx.x;
    int row0 = blockIdx.x * 64;
    int wid  = tid >> 5, lane = tid & 31;

    // per-row mean / rstd (warp per 8 rows)
    for (int r = wid; r < 64; r += 8) {
        const float* xr = x + (size_t)(row0 + r)*INF_;
        float s = 0.f, s2 = 0.f;
        for (int i = lane; i < INF_; i += 32) { float v = xr[i]; s += v; s2 += v*v; }
        #pragma unroll
        for (int o = 16; o; o >>= 1) {
            s  += __shfl_xor_sync(0xffffffffu, s,  o);
            s2 += __shfl_xor_sync(0xffffffffu, s2, o);
        }
        if (lane == 0) {
            float m = s * (1.f/INF_);
            rm[r] = m;
            rr[r] = rsqrtf(s2*(1.f/INF_) - m*m + EPSN);
        }
    }
    if (tid < 128) scb[tid] = g_cb[tid];
    __syncthreads();

    float acc[4][8];
    #pragma unroll
    for (int j = 0; j < 4; j++)
        #pragma unroll
        for (int c = 0; c < 8; c++) acc[j][c] = 0.f;

    int tr = tid >> 4;   // 0..15 -> rows tr*4..tr*4+3
    int tc = tid & 15;   // 0..15 -> cols tc*8..tc*8+7

    for (int kc = 0; kc < INF_; kc += 32) {
        #pragma unroll
        for (int j = 0; j < 8; j++) {          // 64x32 normalized x tile (transposed)
            int idx = tid + j*256;
            int r = idx >> 5, c = idx & 31;
            float v = x[(size_t)(row0 + r)*INF_ + kc + c];
            xsT[c][r] = (v - rm[r]) * rr[r];
        }
        #pragma unroll
        for (int j = 0; j < 16; j++) {         // 32x128 weight tile with g folded
            int idx = tid + j*256;
            int i = idx >> 7, c = idx & 127;
            float w = (c < DD) ? Wk[(kc+i)*DD + c] : Wv[(kc+i)*DD + (c-DD)];
            ws[i][c] = gln[kc + i] * w;
        }
        __syncthreads();
        #pragma unroll
        for (int kk = 0; kk < 32; kk++) {
            float4 a  = *(const float4*)&xsT[kk][tr*4];
            float4 b0 = *(const float4*)&ws[kk][tc*8];
            float4 b1 = *(const float4*)&ws[kk][tc*8 + 4];
            float av[4] = {a.x, a.y, a.z, a.w};
            float bv[8] = {b0.x, b0.y, b0.z, b0.w, b1.x, b1.y, b1.z, b1.w};
            #pragma unroll
            for (int j = 0; j < 4; j++)
                #pragma unroll
                for (int c = 0; c < 8; c++) acc[j][c] += av[j]*bv[c];
        }
        __syncthreads();
    }

    int c0 = tc*8;
    float cbv[8];
    #pragma unroll
    for (int c = 0; c < 8; c++) cbv[c] = scb[c0 + c];
    float* dst = (tc < 8) ? g_k : g_v;
    int cc = (tc < 8) ? c0 : (c0 - DD);
    #pragma unroll
    for (int j = 0; j < 4; j++) {
        int r = row0 + tr*4 + j;
        float4 o0 = make_float4(acc[j][0]+cbv[0], acc[j][1]+cbv[1], acc[j][2]+cbv[2], acc[j][3]+cbv[3]);
        float4 o1 = make_float4(acc[j][4]+cbv[4], acc[j][5]+cbv[5], acc[j][6]+cbv[6], acc[j][7]+cbv[7]);
        *(float4*)(dst + (size_t)r*DD + cc)     = o0;
        *(float4*)(dst + (size_t)r*DD + cc + 4) = o1;
    }
}

// ---------------- slot LN + q projection (tiny) ----------------
__global__ void k_q(const float* __restrict__ Wq, const float* __restrict__ g,
                    const float* __restrict__ bb) {
    int row = blockIdx.x, d = threadIdx.x;   // 64 threads
    __shared__ float sn[64];
    __shared__ float red[2];
    float xv = g_slots[row*DD + d];
    int lane = d & 31, w = d >> 5;
    float s = xv;
    #pragma unroll
    for (int o = 16; o; o >>= 1) s += __shfl_xor_sync(0xffffffffu, s, o);
    if (lane == 0) red[w] = s;
    __syncthreads();
    float m = (red[0] + red[1]) * (1.f/DD);
    __syncthreads();
    float df = xv - m;
    float q2 = df*df;
    #pragma unroll
    for (int o = 16; o; o >>= 1) q2 += __shfl_xor_sync(0xffffffffu, q2, o);
    if (lane == 0) red[w] = q2;
    __syncthreads();
    float var = (red[0] + red[1]) * (1.f/DD);
    float rs = rsqrtf(var + EPSN);
    sn[d] = df*rs*g[d] + bb[d];
    __syncthreads();
    float acc = 0.f;
    #pragma unroll 8
    for (int j = 0; j < DD; j++) acc += sn[j]*Wq[j*DD + d];
    g_q[row*DD + d] = acc;
}

// ---------------- scores = q.k * scale (+mask), written into attn scratch ----------------
__global__ __launch_bounds__(256) void k_scores(const int* __restrict__ mask,
                                                float* __restrict__ attn) {
    __shared__ float ks[64][65];
    __shared__ float qs[KK][64];
    int b = blockIdx.y, s0 = blockIdx.x * 64;
    int tid = threadIdx.x;
    {
        int i0 = tid, i1 = tid + 256;
        qs[i0>>6][i0&63] = g_q[b*KK*DD + i0];
        qs[i1>>6][i1&63] = g_q[b*KK*DD + i1];
    }
    #pragma unroll
    for (int j = 0; j < 16; j++) {
        int idx = tid + j*256;
        int s = idx >> 6, dd = idx & 63;
        ks[s][dd] = g_k[((size_t)(b*SS + s0 + s))*DD + dd];
    }
    __syncthreads();
    int slot = tid >> 5, sl = tid & 31;
    #pragma unroll
    for (int h = 0; h < 2; h++) {
        int s = sl + h*32;
        float acc = 0.f;
        #pragma unroll
        for (int dd = 0; dd < 64; dd++) acc += qs[slot][dd]*ks[s][dd];
        acc *= 0.125f;
        if (mask[b*SS + s0 + s] == 0) acc = -3.402823466e38f;
        attn[((size_t)(b*KK + slot))*SS + s0 + s] = acc;
    }
}

// ---------------- per-(b,slot) softmax stats ----------------
__global__ __launch_bounds__(256) void k_softstats(const float* __restrict__ attn) {
    int row = blockIdx.x;
    const float* sc = attn + (size_t)row*SS;
    int tid = threadIdx.x, lane = tid & 31, w = tid >> 5;
    __shared__ float red[8];
    float m = -FLT_MAX;
    for (int i = tid; i < SS; i += 256) m = fmaxf(m, sc[i]);
    #pragma unroll
    for (int o = 16; o; o >>= 1) m = fmaxf(m, __shfl_xor_sync(0xffffffffu, m, o));
    if (lane == 0) red[w] = m;
    __syncthreads();
    if (tid == 0) {
        float mm = red[0];
        for (int i = 1; i < 8; i++) mm = fmaxf(mm, red[i]);
        red[0] = mm;
    }
    __syncthreads();
    m = red[0];
    __syncthreads();
    float l = 0.f;
    for (int i = tid; i < SS; i += 256) l += expf(sc[i] - m);
    #pragma unroll
    for (int o = 16; o; o >>= 1) l += __shfl_xor_sync(0xffffffffu, l, o);
    if (lane == 0) red[w] = l;
    __syncthreads();
    if (tid == 0) {
        float t = 0.f;
        for (int i = 0; i < 8; i++) t += red[i];
        g_stats[row*2]   = m;
        g_stats[row*2+1] = 1.f/t;
    }
}

// ---------------- partial updates = softmax(scores) @ v per S-chunk (deterministic) ----
__global__ __launch_bounds__(256) void k_updates(float* __restrict__ attn, int last) {
    __shared__ float vs[64][64];
    __shared__ float ps[KK][64];
    __shared__ float st[KK][2];
    int b = blockIdx.y, ch = blockIdx.x, s0 = ch*64;
    int tid = threadIdx.x;
    if (tid < KK*2) st[tid>>1][tid&1] = g_stats[b*KK*2 + tid];
    #pragma unroll
    for (int j = 0; j < 16; j++) {
        int idx = tid + j*256;
        int s = idx >> 6, dd = idx & 63;
        vs[s][dd] = g_v[((size_t)(b*SS + s0 + s))*DD + dd];
    }
    __syncthreads();
    int slot = tid >> 5, sl = tid & 31;
    #pragma unroll
    for (int h = 0; h < 2; h++) {
        int s = sl + h*32;
        size_t off = ((size_t)(b*KK + slot))*SS + s0 + s;
        float p = expf(attn[off] - st[slot][0]) * st[slot][1];
        ps[slot][s] = p;
        if (last) attn[off] = p;   // final iteration leaves normalized attn in d_out
    }
    __syncthreads();
    int dd = tid & 63, sp = tid >> 6;   // sp 0..3 -> slots sp, sp+4
    float a0 = 0.f, a1 = 0.f;
    #pragma unroll
    for (int s = 0; s < 64; s++) {
        float vv = vs[s][dd];
        a0 += ps[sp][s]*vv;
        a1 += ps[sp+4][s]*vv;
    }
    g_updp[(size_t)ch*(BB*KK*DD) + (b*KK + sp)*DD + dd]     = a0;
    g_updp[(size_t)ch*(BB*KK*DD) + (b*KK + sp+4)*DD + dd]   = a1;
}

// ---------------- reduce the 64 S-chunk partials (fixed order -> deterministic) ----
__global__ void k_updred() {
    int idx = blockIdx.x*256 + threadIdx.x;   // 16384
    float s = 0.f;
    #pragma unroll 8
    for (int ch = 0; ch < 64; ch++) s += g_updp[(size_t)ch*(BB*KK*DD) + idx];
    g_upd[idx] = s;
}

// ---------------- GRU cell ----------------
__global__ __launch_bounds__(192) void k_gru(const float* __restrict__ W_ih,
                                             const float* __restrict__ W_hh,
                                             const float* __restrict__ b_ih,
                                             const float* __restrict__ b_hh) {
    __shared__ float su[64], sh[64], gx[192], gh[192];
    int row = blockIdx.x, tid = threadIdx.x;
    if (tid < 64) { su[tid] = g_upd[row*DD + tid]; sh[tid] = g_slots[row*DD + tid]; }
    __syncthreads();
    float ax = b_ih[tid], ah = b_hh[tid];
    #pragma unroll 8
    for (int j = 0; j < 64; j++) {
        ax += su[j]*W_ih[j*192 + tid];
        ah += sh[j]*W_hh[j*192 + tid];
    }
    gx[tid] = ax; gh[tid] = ah;
    __syncthreads();
    if (tid < 64) {
        float r = 1.f/(1.f + expf(-(gx[tid]      + gh[tid])));
        float z = 1.f/(1.f + expf(-(gx[tid+64]   + gh[tid+64])));
        float n = tanhf(gx[tid+128] + r*gh[tid+128]);
        g_slots[row*DD + tid] = (1.f - z)*n + z*sh[tid];
    }
}

// ---------------- final: write slots + validity mask ----------------
__global__ void k_final(const float* __restrict__ Wval, const float* __restrict__ bval,
                        float* __restrict__ out) {
    int row = blockIdx.x, d = threadIdx.x;   // 64 threads
    __shared__ float red[2];
    float s = g_slots[row*DD + d];
    out[row*DD + d] = s;
    float p = s*Wval[d];
    int lane = d & 31, w = d >> 5;
    #pragma unroll
    for (int o = 16; o; o >>= 1) p += __shfl_xor_sync(0xffffffffu, p, o);
    if (lane == 0) red[w] = p;
    __syncthreads();
    if (d == 0) {
        float v = red[0] + red[1] + bval[0];
        out[(size_t)BB*KK*DD + (size_t)BB*KK*SS + row] = (v > 0.f) ? 1.f : 0.f;
    }
}

// ---------------- launch ----------------
extern "C" void kernel_launch(void* const* d_in, const int* in_sizes, int n_in,
                              void* d_out, int out_size) {
    const float* inputs   = (const float*)d_in[0];
    const int*   mask     = (const int*)  d_in[1];
    const float* slot_emb = (const float*)d_in[2];
    const float* Wq       = (const float*)d_in[3];
    const float* Wk       = (const float*)d_in[4];
    const float* Wv       = (const float*)d_in[5];
    const float* W_ih     = (const float*)d_in[6];
    const float* W_hh     = (const float*)d_in[7];
    const float* b_ih     = (const float*)d_in[8];
    const float* b_hh     = (const float*)d_in[9];
    const float* ln_in_g  = (const float*)d_in[10];
    const float* ln_in_b  = (const float*)d_in[11];
    const float* ln_s_g   = (const float*)d_in[12];
    const float* ln_s_b   = (const float*)d_in[13];
    const float* Wval     = (const float*)d_in[14];
    const float* bval     = (const float*)d_in[15];
    float* out  = (float*)d_out;
    float* attn = out + BB*KK*DD;   // attn region of d_out doubles as scores scratch

    k_init<<<64, 256>>>(slot_emb, Wk, Wv, ln_in_b);
    k_proj<<<NROW/64, 256>>>(inputs, Wk, Wv, ln_in_g);
    for (int it = 0; it < 3; it++) {
        k_q<<<BB*KK, 64>>>(Wq, ln_s_g, ln_s_b);
        k_scores<<<dim3(SS/64, BB), 256>>>(mask, attn);
        k_softstats<<<BB*KK, 256>>>(attn);
        k_updates<<<dim3(SS/64, BB), 256>>>(attn, (it == 2) ? 1 : 0);
        k_updred<<<BB*KK*DD/256, 256>>>();
        k_gru<<<BB*KK, 192>>>(W_ih, W_hh, b_ih, b_hh);
    }
    k_final<<<BB*KK, 64>>>(Wval, bval, out);
}

// round 8
// speedup vs baseline: 1.0206x; 1.0206x over previous
#include <cuda_runtime.h>
#include <math.h>
#include <float.h>

#define BB   32
#define SS   4096
#define INF_ 256
#define DD   64
#define KK   8
#define NROW (BB*SS)          // 131072
#define EPSN 1e-5f
#define CS   512              // S-chunk for fused iteration kernel
#define NCH  (SS/CS)          // 8

typedef unsigned long long ULL;

// ---------------- packed fp32x2 helpers (FFMA2 path) ----------------
__device__ __forceinline__ ULL pk2(float lo, float hi) {
    ULL r; asm("mov.b64 %0, {%1, %2};" : "=l"(r) : "f"(lo), "f"(hi)); return r;
}
__device__ __forceinline__ void fma2(ULL& d, ULL a, ULL b) {
    asm("fma.rn.f32x2 %0, %1, %2, %0;" : "+l"(d) : "l"(a), "l"(b));
}
__device__ __forceinline__ float2 upk2(ULL v) {
    float2 f; asm("mov.b64 {%0, %1}, %2;" : "=f"(f.x), "=f"(f.y) : "l"(v)); return f;
}

// ---------------- scratch (device globals; no allocation allowed) ----------------
__device__ __align__(16) float g_k[NROW*DD];             // 33.5 MB
__device__ __align__(16) float g_v[NROW*DD];             // 33.5 MB
__device__ __align__(16) float g_q[BB*KK*DD];
__device__ __align__(16) float g_slots[BB*KK*DD];
__device__ __align__(16) float g_updp[NCH*BB*KK*DD];     // per-chunk partial Sum(e^s * v)
__device__ float g_cst[NCH*BB*KK*2];                     // per-chunk {max, sumexp}
__device__ float g_stats[BB*KK*2];                       // global {max, 1/sum} (for attn pass)
__device__ float g_cb[2*DD];                             // b_ln @ [Wk|Wv]

// ---------------- init: slots broadcast + epilogue bias precompute ----------------
__global__ void k_init(const float* __restrict__ slot_emb,
                       const float* __restrict__ Wk, const float* __restrict__ Wv,
                       const float* __restrict__ lnb) {
    int t = blockIdx.x*blockDim.x + threadIdx.x;
    if (t < BB*KK*DD) g_slots[t] = slot_emb[t % (KK*DD)];
    if (t < 2*DD) {
        float s = 0.f;
        for (int i = 0; i < INF_; i++) {
            float w = (t < DD) ? Wk[i*DD + t] : Wv[i*DD + (t-DD)];
            s += lnb[i]*w;
        }
        g_cb[t] = s;
    }
}

// ---------------- phase 1: fused LN + K/V projection GEMM (FFMA2) ----------------
// 64 rows x 128 cols per block; K-chunks of 32; per-thread 4x8 register tile,
// accumulated as 4x4 packed f32x2 pairs (pair over adjacent columns).
__global__ __launch_bounds__(256) void k_proj(const float* __restrict__ x,
                                              const float* __restrict__ Wk,
                                              const float* __restrict__ Wv,
                                              const float* __restrict__ gln) {
    __shared__ float xsT[32][68];     // [k][row], padded, 16B-aligned rows
    __shared__ float ws[32][128];     // [k][col], g folded in
    __shared__ float rm[64], rr[64], scb[128];

    int tid  = threadIdx.x;
    int row0 = blockIdx.x * 64;
    int wid  = tid >> 5, lane = tid & 31;

    // per-row mean / rstd (warp per 8 rows)
    for (int r = wid; r < 64; r += 8) {
        const float* xr = x + (size_t)(row0 + r)*INF_;
        float s = 0.f, s2 = 0.f;
        for (int i = lane; i < INF_; i += 32) { float v = xr[i]; s += v; s2 += v*v; }
        #pragma unroll
        for (int o = 16; o; o >>= 1) {
            s  += __shfl_xor_sync(0xffffffffu, s,  o);
            s2 += __shfl_xor_sync(0xffffffffu, s2, o);
        }
        if (lane == 0) {
            float m = s * (1.f/INF_);
            rm[r] = m;
            rr[r] = rsqrtf(s2*(1.f/INF_) - m*m + EPSN);
        }
    }
    if (tid < 128) scb[tid] = g_cb[tid];
    __syncthreads();

    ULL acc[4][4];
    #pragma unroll
    for (int j = 0; j < 4; j++)
        #pragma unroll
        for (int c = 0; c < 4; c++) acc[j][c] = 0ull;

    int tr = tid >> 4;   // 0..15 -> rows tr*4..tr*4+3
    int tc = tid & 15;   // 0..15 -> cols tc*8..tc*8+7

    for (int kc = 0; kc < INF_; kc += 32) {
        #pragma unroll
        for (int j = 0; j < 8; j++) {          // 64x32 normalized x tile (transposed)
            int idx = tid + j*256;
            int r = idx >> 5, c = idx & 31;
            float v = x[(size_t)(row0 + r)*INF_ + kc + c];
            xsT[c][r] = (v - rm[r]) * rr[r];
        }
        #pragma unroll
        for (int j = 0; j < 16; j++) {         // 32x128 weight tile with g folded
            int idx = tid + j*256;
            int i = idx >> 7, c = idx & 127;
            float w = (c < DD) ? Wk[(kc+i)*DD + c] : Wv[(kc+i)*DD + (c-DD)];
            ws[i][c] = gln[kc + i] * w;
        }
        __syncthreads();
        #pragma unroll
        for (int kk = 0; kk < 32; kk++) {
            float4 a = *(const float4*)&xsT[kk][tr*4];
            ulonglong2 b0 = *(const ulonglong2*)&ws[kk][tc*8];      // col pairs (0,1),(2,3)
            ulonglong2 b1 = *(const ulonglong2*)&ws[kk][tc*8 + 4];  // col pairs (4,5),(6,7)
            ULL ap[4] = { pk2(a.x,a.x), pk2(a.y,a.y), pk2(a.z,a.z), pk2(a.w,a.w) };
            #pragma unroll
            for (int j = 0; j < 4; j++) {
                fma2(acc[j][0], ap[j], b0.x);
                fma2(acc[j][1], ap[j], b0.y);
                fma2(acc[j][2], ap[j], b1.x);
                fma2(acc[j][3], ap[j], b1.y);
            }
        }
        __syncthreads();
    }

    int c0 = tc*8;
    float cbv[8];
    #pragma unroll
    for (int c = 0; c < 8; c++) cbv[c] = scb[c0 + c];
    float* dst = (tc < 8) ? g_k : g_v;
    int cc = (tc < 8) ? c0 : (c0 - DD);
    #pragma unroll
    for (int j = 0; j < 4; j++) {
        int r = row0 + tr*4 + j;
        float2 p0 = upk2(acc[j][0]), p1 = upk2(acc[j][1]);
        float2 p2 = upk2(acc[j][2]), p3 = upk2(acc[j][3]);
        float4 o0 = make_float4(p0.x+cbv[0], p0.y+cbv[1], p1.x+cbv[2], p1.y+cbv[3]);
        float4 o1 = make_float4(p2.x+cbv[4], p2.y+cbv[5], p3.x+cbv[6], p3.y+cbv[7]);
        *(float4*)(dst + (size_t)r*DD + cc)     = o0;
        *(float4*)(dst + (size_t)r*DD + cc + 4) = o1;
    }
}

// ---------------- slot LN + q projection (tiny) ----------------
__global__ void k_q(const float* __restrict__ Wq, const float* __restrict__ g,
                    const float* __restrict__ bb) {
    int row = blockIdx.x, d = threadIdx.x;   // 64 threads
    __shared__ float sn[64];
    __shared__ float red[2];
    float xv = g_slots[row*DD + d];
    int lane = d & 31, w = d >> 5;
    float s = xv;
    #pragma unroll
    for (int o = 16; o; o >>= 1) s += __shfl_xor_sync(0xffffffffu, s, o);
    if (lane == 0) red[w] = s;
    __syncthreads();
    float m = (red[0] + red[1]) * (1.f/DD);
    __syncthreads();
    float df = xv - m;
    float q2 = df*df;
    #pragma unroll
    for (int o = 16; o; o >>= 1) q2 += __shfl_xor_sync(0xffffffffu, q2, o);
    if (lane == 0) red[w] = q2;
    __syncthreads();
    float var = (red[0] + red[1]) * (1.f/DD);
    float rs = rsqrtf(var + EPSN);
    sn[d] = df*rs*g[d] + bb[d];
    __syncthreads();
    float acc = 0.f;
    #pragma unroll 8
    for (int j = 0; j < DD; j++) acc += sn[j]*Wq[j*DD + d];
    g_q[row*DD + d] = acc;
}

// ---------------- fused iteration: scores + chunk-softmax + partial updates ------
// grid (NCH, BB), 256 threads. Each block: 512-s chunk, all 8 slots.
// K and V each read exactly once from HBM per iteration.
__global__ __launch_bounds__(256) void k_iter(const int* __restrict__ mask,
                                              float* __restrict__ attn, int last) {
    __shared__ float qs[KK][64];      // 2 KB
    __shared__ float ps[KK][CS];      // 16 KB : raw scores, then probabilities
    int b = blockIdx.y, ch = blockIdx.x, s0 = ch*CS;
    int tid = threadIdx.x;

    for (int j = tid; j < KK*DD; j += 256) ((float*)qs)[j] = g_q[b*KK*DD + j];
    __syncthreads();

    // ---- phase A: scores for s = s0+tid and s0+tid+256, all 8 slots (FFMA2) ----
    const float* kb = g_k + ((size_t)(b*SS + s0))*DD;
    ULL acc[2][KK];
    #pragma unroll
    for (int h = 0; h < 2; h++)
        #pragma unroll
        for (int sl = 0; sl < KK; sl++) acc[h][sl] = 0ull;

    #pragma unroll
    for (int i = 0; i < 16; i++) {
        ulonglong2 ka = *(const ulonglong2*)(kb + (size_t)tid*DD + i*4);
        ulonglong2 kb2 = *(const ulonglong2*)(kb + (size_t)(tid+256)*DD + i*4);
        #pragma unroll
        for (int sl = 0; sl < KK; sl++) {
            ulonglong2 qp = *(const ulonglong2*)&qs[sl][i*4];   // warp-uniform -> LDS broadcast
            fma2(acc[0][sl], qp.x, ka.x);
            fma2(acc[0][sl], qp.y, ka.y);
            fma2(acc[1][sl], qp.x, kb2.x);
            fma2(acc[1][sl], qp.y, kb2.y);
        }
    }
    int mk0 = mask[b*SS + s0 + tid];
    int mk1 = mask[b*SS + s0 + tid + 256];
    #pragma unroll
    for (int h = 0; h < 2; h++) {
        int mk = h ? mk1 : mk0;
        #pragma unroll
        for (int sl = 0; sl < KK; sl++) {
            float2 t = upk2(acc[h][sl]);
            float sc = (t.x + t.y) * 0.125f;
            if (mk == 0) sc = -3.402823466e38f;
            ps[sl][tid + h*256] = sc;
            if (last) attn[((size_t)(b*KK + sl))*SS + s0 + tid + h*256] = sc;
        }
    }
    __syncthreads();

    // ---- phase B: per-slot chunk max + sumexp; ps -> probabilities (warp per slot) ----
    {
        int w = tid >> 5, lane = tid & 31;
        float m = -FLT_MAX;
        #pragma unroll
        for (int j = 0; j < CS/32; j++) m = fmaxf(m, ps[w][lane + 32*j]);
        #pragma unroll
        for (int o = 16; o; o >>= 1) m = fmaxf(m, __shfl_xor_sync(0xffffffffu, m, o));
        float l = 0.f;
        #pragma unroll
        for (int j = 0; j < CS/32; j++) {
            float p = expf(ps[w][lane + 32*j] - m);
            ps[w][lane + 32*j] = p;
            l += p;
        }
        #pragma unroll
        for (int o = 16; o; o >>= 1) l += __shfl_xor_sync(0xffffffffu, l, o);
        if (lane == 0) {
            g_cst[((ch*BB + b)*KK + w)*2]     = m;
            g_cst[((ch*BB + b)*KK + w)*2 + 1] = l;
        }
    }
    __syncthreads();

    // ---- phase C: partial update U_c[slot][d] = sum_s p * v (FFMA2 over d-pairs) ----
    {
        int dp = tid & 31;       // d-pair index -> d = 2*dp
        int sl = tid >> 5;       // slot
        const float* vp = g_v + ((size_t)(b*SS + s0))*DD + 2*dp;
        ULL a0 = 0ull, a1 = 0ull;
        #pragma unroll 4
        for (int s = 0; s < CS; s += 2) {
            ULL v0 = *(const ULL*)(vp + (size_t)s*DD);
            ULL v1 = *(const ULL*)(vp + (size_t)(s+1)*DD);
            float p0 = ps[sl][s], p1 = ps[sl][s+1];
            fma2(a0, pk2(p0,p0), v0);
            fma2(a1, pk2(p1,p1), v1);
        }
        float2 r0 = upk2(a0), r1 = upk2(a1);
        float2 r = make_float2(r0.x + r1.x, r0.y + r1.y);
        *(float2*)&g_updp[((size_t)(ch*BB + b)*KK + sl)*DD + 2*dp] = r;
    }
}

// ---------------- GRU cell with deterministic chunk-combine prologue ----------------
__global__ __launch_bounds__(192) void k_gru(const float* __restrict__ W_ih,
                                             const float* __restrict__ W_hh,
                                             const float* __restrict__ b_ih,
                                             const float* __restrict__ b_hh) {
    __shared__ float su[64], sh[64], gx[192], gh[192];
    int row = blockIdx.x, tid = threadIdx.x;   // row = b*KK + slot
    if (tid < 64) {
        float m = -FLT_MAX;
        #pragma unroll
        for (int ch = 0; ch < NCH; ch++)
            m = fmaxf(m, g_cst[(ch*BB*KK + row)*2]);
        float l = 0.f, U = 0.f;
        #pragma unroll
        for (int ch = 0; ch < NCH; ch++) {
            float w = expf(g_cst[(ch*BB*KK + row)*2] - m);
            l += g_cst[(ch*BB*KK + row)*2 + 1] * w;
            U += g_updp[((size_t)ch*BB*KK + row)*DD + tid] * w;
        }
        su[tid] = U / l;
        sh[tid] = g_slots[row*DD + tid];
        if (tid == 0) { g_stats[row*2] = m; g_stats[row*2+1] = 1.f/l; }
    }
    __syncthreads();
    float ax = b_ih[tid], ah = b_hh[tid];
    #pragma unroll 8
    for (int j = 0; j < 64; j++) {
        ax += su[j]*W_ih[j*192 + tid];
        ah += sh[j]*W_hh[j*192 + tid];
    }
    gx[tid] = ax; gh[tid] = ah;
    __syncthreads();
    if (tid < 64) {
        float r = 1.f/(1.f + expf(-(gx[tid]      + gh[tid])));
        float z = 1.f/(1.f + expf(-(gx[tid+64]   + gh[tid+64])));
        float n = tanhf(gx[tid+128] + r*gh[tid+128]);
        g_slots[row*DD + tid] = (1.f - z)*n + z*sh[tid];
    }
}

// ---------------- normalize raw scores in d_out into attn probabilities ----------------
__global__ __launch_bounds__(256) void k_attn(float* __restrict__ attn) {
    int row = blockIdx.x;
    float m  = g_stats[row*2];
    float rl = g_stats[row*2 + 1];
    float* a = attn + (size_t)row*SS;
    for (int i = threadIdx.x; i < SS; i += 256)
        a[i] = expf(a[i] - m) * rl;
}

// ---------------- final: write slots + validity mask ----------------
__global__ void k_final(const float* __restrict__ Wval, const float* __restrict__ bval,
                        float* __restrict__ out) {
    int row = blockIdx.x, d = threadIdx.x;   // 64 threads
    __shared__ float red[2];
    float s = g_slots[row*DD + d];
    out[row*DD + d] = s;
    float p = s*Wval[d];
    int lane = d & 31, w = d >> 5;
    #pragma unroll
    for (int o = 16; o; o >>= 1) p += __shfl_xor_sync(0xffffffffu, p, o);
    if (lane == 0) red[w] = p;
    __syncthreads();
    if (d == 0) {
        float v = red[0] + red[1] + bval[0];
        out[(size_t)BB*KK*DD + (size_t)BB*KK*SS + row] = (v > 0.f) ? 1.f : 0.f;
    }
}

// ---------------- launch ----------------
extern "C" void kernel_launch(void* const* d_in, const int* in_sizes, int n_in,
                              void* d_out, int out_size) {
    const float* inputs   = (const float*)d_in[0];
    const int*   mask     = (const int*)  d_in[1];
    const float* slot_emb = (const float*)d_in[2];
    const float* Wq       = (const float*)d_in[3];
    const float* Wk       = (const float*)d_in[4];
    const float* Wv       = (const float*)d_in[5];
    const float* W_ih     = (const float*)d_in[6];
    const float* W_hh     = (const float*)d_in[7];
    const float* b_ih     = (const float*)d_in[8];
    const float* b_hh     = (const float*)d_in[9];
    const float* ln_in_g  = (const float*)d_in[10];
    const float* ln_in_b  = (const float*)d_in[11];
    const float* ln_s_g   = (const float*)d_in[12];
    const float* ln_s_b   = (const float*)d_in[13];
    const float* Wval     = (const float*)d_in[14];
    const float* bval     = (const float*)d_in[15];
    float* out  = (float*)d_out;
    float* attn = out + BB*KK*DD;   // attn region of d_out doubles as raw-score scratch

    k_init<<<64, 256>>>(slot_emb, Wk, Wv, ln_in_b);
    k_proj<<<NROW/64, 256>>>(inputs, Wk, Wv, ln_in_g);
    for (int it = 0; it < 3; it++) {
        k_q<<<BB*KK, 64>>>(Wq, ln_s_g, ln_s_b);
        k_iter<<<dim3(NCH, BB), 256>>>(mask, attn, (it == 2) ? 1 : 0);
        k_gru<<<BB*KK, 192>>>(W_ih, W_hh, b_ih, b_hh);
    }
    k_attn<<<BB*KK, 256>>>(attn);
    k_final<<<BB*KK, 64>>>(Wval, bval, out);
}